// round 1
// baseline (speedup 1.0000x reference)
#include <cuda_runtime.h>
#include <cstdint>

// LSTM CellForecaster: B=4096, T=512, H=128, IN=2, OUT=2, FUTURE=50
// Persistent per-batch-slice CTAs, no grid sync (batch rows independent).
// fp32 throughout; recurrent GEMM uses packed fma.rn.f32x2 (2x FFMA rate on B300).

#define HID    128
#define GATES  512
#define BB     32          // batch rows per CTA
#define TENC   512
#define FUT    50
#define NSTEP  (TENC + FUT)
#define THREADS 128
#define WPITCH 132         // W chunk row pitch (floats): conflict-free LDS.128
#define HPITCH 36          // h/c/tmp row pitch (floats): 4-way max on epilogue stores

struct alignas(16) SmemLayout {
    float W[2][128 * WPITCH];   // double-buffered gate chunk [128 gates][128 k]
    float h[HID * HPITCH];      // h[k][b] k-major (batch contiguous for f32x2 pairs)
    float c[HID * HPITCH];
    float tg[HID * HPITCH];     // sigmoid(i) staging
    float bias[GATES];          // b_ih + b_hh
    float wih[GATES * 2];
    float fcw[2 * HID];
    float fcb[2];
    float xin[BB * 2];          // current step input (x_t or fed-back y)
};

__device__ __forceinline__ uint32_t smem_u32(const void* p) {
    uint32_t a;
    asm("{ .reg .u64 t; cvta.to.shared.u64 t, %1; cvt.u32.u64 %0, t; }"
        : "=r"(a) : "l"(p));
    return a;
}
__device__ __forceinline__ unsigned long long pk2(float x, float y) {
    unsigned long long r;
    asm("mov.b64 %0, {%1,%2};" : "=l"(r) : "f"(x), "f"(y));
    return r;
}
__device__ __forceinline__ void upk2(unsigned long long v, float& x, float& y) {
    asm("mov.b64 {%0,%1}, %2;" : "=f"(x), "=f"(y) : "l"(v));
}
__device__ __forceinline__ unsigned long long fma2(unsigned long long a,
                                                   unsigned long long b,
                                                   unsigned long long c) {
    unsigned long long d;
    asm("fma.rn.f32x2 %0, %1, %2, %3;" : "=l"(d) : "l"(a), "l"(b), "l"(c));
    return d;
}
__device__ __forceinline__ float sigf(float x) { return 1.f / (1.f + __expf(-x)); }
__device__ __forceinline__ float tanh_(float x) { return 2.f / (1.f + __expf(-2.f * x)) - 1.f; }

__device__ __forceinline__ void cpa16(uint32_t dst, const float* src) {
    asm volatile("cp.async.cg.shared.global [%0], [%1], 16;" :: "r"(dst), "l"(src));
}
#define CP_COMMIT() asm volatile("cp.async.commit_group;")
#define CP_WAIT0()  asm volatile("cp.async.wait_group 0;")

__global__ void __launch_bounds__(THREADS, 1)
lstm_forecast_kernel(const float* __restrict__ x,
                     const float* __restrict__ Wih,
                     const float* __restrict__ Whh,
                     const float* __restrict__ bih,
                     const float* __restrict__ bhh,
                     const float* __restrict__ fcw,
                     const float* __restrict__ fcb,
                     float* __restrict__ out)
{
    extern __shared__ char smraw[];
    SmemLayout& sm = *reinterpret_cast<SmemLayout*>(smraw);

    const int tid = threadIdx.x;
    const int b0  = blockIdx.x * BB;
    const int tx  = tid & 31;    // 32 gate-groups
    const int ty  = tid >> 5;    // 4 batch-groups of 8

    // ---- one-time init ----
    for (int i = tid; i < HID * HPITCH; i += THREADS) { sm.h[i] = 0.f; sm.c[i] = 0.f; }
    for (int g = tid; g < GATES; g += THREADS) {
        sm.bias[g]      = bih[g] + bhh[g];
        sm.wih[g*2 + 0] = Wih[g*2 + 0];
        sm.wih[g*2 + 1] = Wih[g*2 + 1];
    }
    for (int i = tid; i < 2 * HID; i += THREADS) sm.fcw[i] = fcw[i];
    if (tid < 2) sm.fcb[tid] = fcb[tid];

    const uint32_t wbase0 = smem_u32(&sm.W[0][0]);
    const uint32_t wbase1 = smem_u32(&sm.W[1][0]);

    auto stage = [&](int chunk, int buf) {
        const float*  src = Whh + chunk * (128 * HID);
        const uint32_t wb = buf ? wbase1 : wbase0;
        #pragma unroll
        for (int r = 0; r < 32; r++) {
            int e   = tid + THREADS * r;          // 0..4095 float4 slots
            int row = e >> 5;
            int c4  = (e & 31) << 2;
            cpa16(wb + (uint32_t)(row * WPITCH + c4) * 4u, src + row * HID + c4);
        }
        CP_COMMIT();
    };

    stage(0, 0);  // prefetch chunk 0 (i-gates)

    for (int s = 0; s < NSTEP; s++) {
        // ---- step input: x_t (encode) or y = h@fc_w^T + fc_b (forecast) ----
        if (s < TENC) {
            if (tid < 64) {
                int b = tid >> 1, i = tid & 1;
                sm.xin[b * 2 + i] = x[(size_t)(b0 + b) * (TENC * 2) + s * 2 + i];
            }
        } else {
            if (tid < 64) {
                int b = tid >> 1, o = tid & 1;
                float acc = sm.fcb[o];
                const float* fr = &sm.fcw[o * HID];
                #pragma unroll 8
                for (int k = 0; k < HID; k++) acc += sm.h[k * HPITCH + b] * fr[k];
                sm.xin[b * 2 + o] = acc;
                out[(size_t)(b0 + b) * (FUT * 2) + (s - TENC) * 2 + o] = acc;
            }
        }
        __syncthreads();

        float hstash[4][8];

        for (int ch = 0; ch < 4; ch++) {
            CP_WAIT0();          // chunk ch landed
            __syncthreads();     // visible CTA-wide; prev chunk's buffer is free
            if (!(s == NSTEP - 1 && ch == 3))
                stage((ch + 1) & 3, (ch + 1) & 1);  // prefetch next chunk

            // ---- accumulator init: bias + x @ W_ih^T ----
            unsigned long long acc[4][4];
            #pragma unroll
            for (int gi = 0; gi < 4; gi++) {
                int G = ch * 128 + tx + 32 * gi;
                float bsv = sm.bias[G];
                float w0 = sm.wih[G * 2], w1 = sm.wih[G * 2 + 1];
                #pragma unroll
                for (int p = 0; p < 4; p++) {
                    int bA = ty * 8 + 2 * p;
                    float va = bsv + sm.xin[bA*2 + 0]*w0 + sm.xin[bA*2 + 1]*w1;
                    float vb = bsv + sm.xin[bA*2 + 2]*w0 + sm.xin[bA*2 + 3]*w1;
                    acc[gi][p] = pk2(va, vb);
                }
            }

            // ---- GEMM: gates[128, BB] += Wchunk[128,128] @ h[128, BB] ----
            const float* Wb = &sm.W[ch & 1][0];
            const float* hp = &sm.h[ty * 8];
            #pragma unroll 2
            for (int k0 = 0; k0 < HID; k0 += 4) {
                float4 wq[4];
                #pragma unroll
                for (int gi = 0; gi < 4; gi++)
                    wq[gi] = *reinterpret_cast<const float4*>(&Wb[(tx + 32*gi) * WPITCH + k0]);
                #pragma unroll
                for (int kk = 0; kk < 4; kk++) {
                    ulonglong2 ha = *reinterpret_cast<const ulonglong2*>(&hp[(k0 + kk) * HPITCH]);
                    ulonglong2 hb = *reinterpret_cast<const ulonglong2*>(&hp[(k0 + kk) * HPITCH + 4]);
                    #pragma unroll
                    for (int gi = 0; gi < 4; gi++) {
                        float w = (&wq[gi].x)[kk];
                        unsigned long long wp = pk2(w, w);
                        acc[gi][0] = fma2(wp, ha.x, acc[gi][0]);
                        acc[gi][1] = fma2(wp, ha.y, acc[gi][1]);
                        acc[gi][2] = fma2(wp, hb.x, acc[gi][2]);
                        acc[gi][3] = fma2(wp, hb.y, acc[gi][3]);
                    }
                }
            }

            // ---- per-chunk pointwise (PyTorch gate order i,f,g,o) ----
            #pragma unroll
            for (int gi = 0; gi < 4; gi++) {
                int hrow = tx + 32 * gi;  // chunk-local gate == hidden index
                #pragma unroll
                for (int p = 0; p < 4; p++) {
                    float va, vb;
                    upk2(acc[gi][p], va, vb);
                    int i0 = hrow * HPITCH + ty * 8 + 2 * p;
                    if (ch == 0) {                 // i
                        sm.tg[i0]     = sigf(va);
                        sm.tg[i0 + 1] = sigf(vb);
                    } else if (ch == 1) {          // f: c *= sig(f)
                        sm.c[i0]     *= sigf(va);
                        sm.c[i0 + 1] *= sigf(vb);
                    } else if (ch == 2) {          // g: c += sig(i)*tanh(g)
                        sm.c[i0]     += sm.tg[i0]     * tanh_(va);
                        sm.c[i0 + 1] += sm.tg[i0 + 1] * tanh_(vb);
                    } else {                       // o: h = sig(o)*tanh(c)
                        hstash[gi][2*p]     = sigf(va) * tanh_(sm.c[i0]);
                        hstash[gi][2*p + 1] = sigf(vb) * tanh_(sm.c[i0 + 1]);
                    }
                }
            }

            if (ch == 3) {
                __syncthreads();   // all threads done reading old h
                #pragma unroll
                for (int gi = 0; gi < 4; gi++) {
                    int hrow = tx + 32 * gi;
                    #pragma unroll
                    for (int p = 0; p < 8; p++)
                        sm.h[hrow * HPITCH + ty * 8 + p] = hstash[gi][p];
                }
                __syncthreads();   // new h visible before next step reads it
            }
        }
    }
}

extern "C" void kernel_launch(void* const* d_in, const int* in_sizes, int n_in,
                              void* d_out, int out_size) {
    const float* x    = (const float*)d_in[0];
    const float* Wih  = (const float*)d_in[1];
    const float* Whh  = (const float*)d_in[2];
    const float* bih  = (const float*)d_in[3];
    const float* bhh  = (const float*)d_in[4];
    const float* fcw  = (const float*)d_in[5];
    const float* fcb  = (const float*)d_in[6];
    float* out = (float*)d_out;

    const int smem_bytes = (int)sizeof(SmemLayout);
    cudaFuncSetAttribute(lstm_forecast_kernel,
                         cudaFuncAttributeMaxDynamicSharedMemorySize, smem_bytes);

    lstm_forecast_kernel<<<4096 / BB, THREADS, smem_bytes>>>(
        x, Wih, Whh, bih, bhh, fcw, fcb, out);
}

// round 2
// speedup vs baseline: 1.1542x; 1.1542x over previous
#include <cuda_runtime.h>
#include <cstdint>

// LSTM CellForecaster: B=4096, T=512, H=128, IN=2, OUT=2, FUTURE=50
// Persistent per-batch-slice CTAs (128 CTAs x 256 thr). fp32, fma.rn.f32x2.
// Dot product packed ACROSS K (h stored batch-major) -> no operand-packing movs.
// c and sigmoid(i) live entirely in registers.

#define HID    128
#define GATES  512
#define BB     32
#define TENC   512
#define FUT    50
#define NSTEP  (TENC + FUT)
#define THREADS 256
#define WPITCH 132       // W chunk row pitch (floats), conflict-free LDS.128
#define TPITCH 132       // hT row pitch (floats)

struct alignas(16) SmemLayout {
    float W[2][128 * WPITCH];   // double-buffered gate chunk [128 gates][128 k]
    float hT[BB * TPITCH];      // h batch-major: hT[b][k]
    float bias[GATES];          // b_ih + b_hh
    float wih[GATES * 2];
    float fcw[2 * HID];
    float fcb[2];
    float xin[BB * 2];          // current step input (x_t or fed-back y)
};

__device__ __forceinline__ uint32_t smem_u32(const void* p) {
    uint32_t a;
    asm("{ .reg .u64 t; cvta.to.shared.u64 t, %1; cvt.u32.u64 %0, t; }"
        : "=r"(a) : "l"(p));
    return a;
}
__device__ __forceinline__ void upk2(unsigned long long v, float& x, float& y) {
    asm("mov.b64 {%0,%1}, %2;" : "=f"(x), "=f"(y) : "l"(v));
}
__device__ __forceinline__ unsigned long long fma2(unsigned long long a,
                                                   unsigned long long b,
                                                   unsigned long long c) {
    unsigned long long d;
    asm("fma.rn.f32x2 %0, %1, %2, %3;" : "=l"(d) : "l"(a), "l"(b), "l"(c));
    return d;
}
__device__ __forceinline__ float sigf(float x) { return 1.f / (1.f + __expf(-x)); }
__device__ __forceinline__ float tanh_(float x) { return 2.f / (1.f + __expf(-2.f * x)) - 1.f; }

__device__ __forceinline__ void cpa16(uint32_t dst, const float* src) {
    asm volatile("cp.async.cg.shared.global [%0], [%1], 16;" :: "r"(dst), "l"(src));
}
#define CP_COMMIT() asm volatile("cp.async.commit_group;")
#define CP_WAIT0()  asm volatile("cp.async.wait_group 0;")

__global__ void __launch_bounds__(THREADS, 1)
lstm_forecast_kernel(const float* __restrict__ x,
                     const float* __restrict__ Wih,
                     const float* __restrict__ Whh,
                     const float* __restrict__ bih,
                     const float* __restrict__ bhh,
                     const float* __restrict__ fcw,
                     const float* __restrict__ fcb,
                     float* __restrict__ out)
{
    extern __shared__ char smraw[];
    SmemLayout& sm = *reinterpret_cast<SmemLayout*>(smraw);

    const int tid  = threadIdx.x;
    const int bat0 = blockIdx.x * BB;
    const int tx   = tid & 31;          // gate-row lane
    const int ty   = (tid >> 5) & 3;    // batch group (8 rows)
    const int wg   = tid >> 7;          // gate-row half (0: rows 0-63, 1: 64-127)
    const int row0 = wg * 64 + tx;      // +32*gi for gi=0,1
    const int bt0  = ty * 8;

    // ---- one-time init ----
    for (int i = tid; i < BB * TPITCH; i += THREADS) sm.hT[i] = 0.f;
    for (int g = tid; g < GATES; g += THREADS) {
        sm.bias[g]      = bih[g] + bhh[g];
        sm.wih[g*2 + 0] = Wih[g*2 + 0];
        sm.wih[g*2 + 1] = Wih[g*2 + 1];
    }
    for (int i = tid; i < 2 * HID; i += THREADS) sm.fcw[i] = fcw[i];
    if (tid < 2) sm.fcb[tid] = fcb[tid];

    const uint32_t wbase0 = smem_u32(&sm.W[0][0]);
    const uint32_t wbase1 = smem_u32(&sm.W[1][0]);

    auto stage = [&](int chunk, int buf) {
        const float*  src = Whh + chunk * (128 * HID);
        const uint32_t wb = buf ? wbase1 : wbase0;
        #pragma unroll
        for (int r = 0; r < 16; r++) {
            int e   = tid + THREADS * r;          // 0..4095 float4 slots
            int row = e >> 5;
            int c4  = (e & 31) << 2;
            cpa16(wb + (uint32_t)(row * WPITCH + c4) * 4u, src + row * HID + c4);
        }
        CP_COMMIT();
    };

    stage(0, 0);  // prefetch chunk 0 (i-gates)

    // register-resident cell state + sigmoid(i) staging (thread owns fixed
    // (hidden-row, batch) tiles identical across chunks and steps)
    float creg[2][8];
    float ti[2][8];
    #pragma unroll
    for (int gi = 0; gi < 2; gi++)
        #pragma unroll
        for (int p = 0; p < 8; p++) creg[gi][p] = 0.f;

    for (int s = 0; s < NSTEP; s++) {
        // ---- step input: x_t (encode) or y = h@fc_w^T + fc_b (forecast) ----
        if (s < TENC) {
            if (tid < 64) {
                int b = tid >> 1, i = tid & 1;
                sm.xin[b * 2 + i] = x[(size_t)(bat0 + b) * (TENC * 2) + s * 2 + i];
            }
        } else {
            if (tid < 64) {
                int b = tid >> 1, o = tid & 1;
                float acc = sm.fcb[o];
                const float* fr = &sm.fcw[o * HID];
                const float* hr = &sm.hT[b * TPITCH];
                #pragma unroll 8
                for (int k = 0; k < HID; k++) acc += hr[k] * fr[k];
                sm.xin[b * 2 + o] = acc;
                out[(size_t)(bat0 + b) * (FUT * 2) + (s - TENC) * 2 + o] = acc;
            }
        }
        __syncthreads();

        float hst[2][8];

        for (int ch = 0; ch < 4; ch++) {
            CP_WAIT0();          // chunk ch landed
            __syncthreads();     // visible CTA-wide; prev buffer now free
            if (!(s == NSTEP - 1 && ch == 3))
                stage((ch + 1) & 3, (ch + 1) & 1);

            // ---- GEMM: gates[g][b] = sum_k Wchunk[g][k] * hT[b][k] ----
            unsigned long long acc[2][8];
            #pragma unroll
            for (int gi = 0; gi < 2; gi++)
                #pragma unroll
                for (int p = 0; p < 8; p++) acc[gi][p] = 0ull;

            const float* Wb = &sm.W[ch & 1][0];
            #pragma unroll 8
            for (int k0 = 0; k0 < HID; k0 += 4) {
                ulonglong2 w0 = *reinterpret_cast<const ulonglong2*>(&Wb[row0 * WPITCH + k0]);
                ulonglong2 w1 = *reinterpret_cast<const ulonglong2*>(&Wb[(row0 + 32) * WPITCH + k0]);
                #pragma unroll
                for (int p = 0; p < 8; p++) {
                    ulonglong2 hv = *reinterpret_cast<const ulonglong2*>(&sm.hT[(bt0 + p) * TPITCH + k0]);
                    acc[0][p] = fma2(w0.x, hv.x, acc[0][p]);
                    acc[0][p] = fma2(w0.y, hv.y, acc[0][p]);
                    acc[1][p] = fma2(w1.x, hv.x, acc[1][p]);
                    acc[1][p] = fma2(w1.y, hv.y, acc[1][p]);
                }
            }

            // ---- horizontal add + bias + x@W_ih^T, then pointwise ----
            #pragma unroll
            for (int gi = 0; gi < 2; gi++) {
                const int G  = ch * 128 + row0 + 32 * gi;
                const float bsv = sm.bias[G];
                const float w0 = sm.wih[G * 2], w1 = sm.wih[G * 2 + 1];
                #pragma unroll
                for (int p = 0; p < 8; p++) {
                    const int b = bt0 + p;
                    float va, vb;
                    upk2(acc[gi][p], va, vb);
                    float gate = va + vb + bsv + sm.xin[b*2]*w0 + sm.xin[b*2+1]*w1;
                    if (ch == 0) {                         // i
                        ti[gi][p] = sigf(gate);
                    } else if (ch == 1) {                  // f
                        creg[gi][p] *= sigf(gate);
                    } else if (ch == 2) {                  // g
                        creg[gi][p] += ti[gi][p] * tanh_(gate);
                    } else {                               // o
                        hst[gi][p] = sigf(gate) * tanh_(creg[gi][p]);
                    }
                }
            }

            if (ch == 3) {
                __syncthreads();   // all warps done reading old hT
                #pragma unroll
                for (int gi = 0; gi < 2; gi++) {
                    const int hrow = row0 + 32 * gi;
                    #pragma unroll
                    for (int p = 0; p < 8; p++)
                        sm.hT[(bt0 + p) * TPITCH + hrow] = hst[gi][p];
                }
                __syncthreads();   // new h visible for fc-head / next step
            }
        }
    }
}

extern "C" void kernel_launch(void* const* d_in, const int* in_sizes, int n_in,
                              void* d_out, int out_size) {
    const float* x    = (const float*)d_in[0];
    const float* Wih  = (const float*)d_in[1];
    const float* Whh  = (const float*)d_in[2];
    const float* bih  = (const float*)d_in[3];
    const float* bhh  = (const float*)d_in[4];
    const float* fcw  = (const float*)d_in[5];
    const float* fcb  = (const float*)d_in[6];
    float* out = (float*)d_out;

    const int smem_bytes = (int)sizeof(SmemLayout);
    cudaFuncSetAttribute(lstm_forecast_kernel,
                         cudaFuncAttributeMaxDynamicSharedMemorySize, smem_bytes);

    lstm_forecast_kernel<<<4096 / BB, THREADS, smem_bytes>>>(
        x, Wih, Whh, bih, bhh, fcw, fcb, out);
}